// round 1
// baseline (speedup 1.0000x reference)
#include <cuda_runtime.h>
#include <cuda_bf16.h>

// Problem: x [8192,1024] f32, weight [1024,1024] f32.
// out = ((norm @ norm^T) @ x) @ W  reassociated as  norm @ ((norm^T @ x) @ W)
// norm = x / max(||x_row||_2, 1e-12)

#define NROWS 8192
#define DIM   1024

// Scratch (device globals -- no allocation allowed)
__device__ float g_norm[NROWS * DIM];   // 32 MB
__device__ float g_G[DIM * DIM];        // 4 MB
__device__ float g_H[DIM * DIM];        // 4 MB

// ---------------------------------------------------------------------------
// Row L2 normalize: one block per row, 256 threads, float4 loads.
// ---------------------------------------------------------------------------
__global__ void rownorm_kernel(const float* __restrict__ x, float* __restrict__ out) {
    const int row = blockIdx.x;
    const float4* xr = reinterpret_cast<const float4*>(x + (size_t)row * DIM);
    float4* orow = reinterpret_cast<float4*>(out + (size_t)row * DIM);

    // DIM/4 = 256 float4 per row, one per thread
    float4 v = xr[threadIdx.x];
    float s = v.x * v.x + v.y * v.y + v.z * v.z + v.w * v.w;

    // warp reduce
    #pragma unroll
    for (int off = 16; off > 0; off >>= 1)
        s += __shfl_down_sync(0xFFFFFFFFu, s, off);

    __shared__ float warp_s[8];
    const int lane = threadIdx.x & 31;
    const int wid = threadIdx.x >> 5;
    if (lane == 0) warp_s[wid] = s;
    __syncthreads();

    __shared__ float inv_norm;
    if (threadIdx.x == 0) {
        float t = 0.f;
        #pragma unroll
        for (int i = 0; i < 8; i++) t += warp_s[i];
        inv_norm = 1.0f / fmaxf(sqrtf(t), 1e-12f);
    }
    __syncthreads();

    const float inv = inv_norm;
    v.x *= inv; v.y *= inv; v.z *= inv; v.w *= inv;
    orow[threadIdx.x] = v;
}

// ---------------------------------------------------------------------------
// Tiled SGEMM: BM=BN=64, BK=16, 256 threads (16x16), 4x4 micro-tile.
// All dimensions are multiples of tile sizes -> no bounds checks.
// ---------------------------------------------------------------------------
#define BM 64
#define BN 64
#define BK 16
#define TM 4
#define TN 4

// C[M,N] = A^T * B, with A stored [K,M] row-major, B stored [K,N] row-major.
__global__ void sgemm_tn(const float* __restrict__ A, const float* __restrict__ B,
                         float* __restrict__ C, int M, int N, int K) {
    __shared__ float As[BK][BM];
    __shared__ float Bs[BK][BN];

    const int t = threadIdx.x;
    const int tx = t & 15;         // 0..15 -> N
    const int ty = t >> 4;         // 0..15 -> M
    const int m0 = blockIdx.y * BM;
    const int n0 = blockIdx.x * BN;

    // load mapping: 256 threads * float4 = 1024 floats = 16x64 tile
    const int lk = t >> 4;          // 0..15  (K within tile)
    const int lm = (t & 15) << 2;   // 0,4,...,60

    float acc[TM][TN];
    #pragma unroll
    for (int i = 0; i < TM; i++)
        #pragma unroll
        for (int j = 0; j < TN; j++) acc[i][j] = 0.f;

    for (int k0 = 0; k0 < K; k0 += BK) {
        float4 av = *reinterpret_cast<const float4*>(&A[(size_t)(k0 + lk) * M + m0 + lm]);
        float4 bv = *reinterpret_cast<const float4*>(&B[(size_t)(k0 + lk) * N + n0 + lm]);
        *reinterpret_cast<float4*>(&As[lk][lm]) = av;
        *reinterpret_cast<float4*>(&Bs[lk][lm]) = bv;
        __syncthreads();

        #pragma unroll
        for (int kk = 0; kk < BK; kk++) {
            float4 ar = *reinterpret_cast<float4*>(&As[kk][ty * TM]);
            float4 br = *reinterpret_cast<float4*>(&Bs[kk][tx * TN]);
            float a[TM] = {ar.x, ar.y, ar.z, ar.w};
            float b[TN] = {br.x, br.y, br.z, br.w};
            #pragma unroll
            for (int i = 0; i < TM; i++)
                #pragma unroll
                for (int j = 0; j < TN; j++)
                    acc[i][j] += a[i] * b[j];
        }
        __syncthreads();
    }

    #pragma unroll
    for (int i = 0; i < TM; i++) {
        float4 cv = make_float4(acc[i][0], acc[i][1], acc[i][2], acc[i][3]);
        *reinterpret_cast<float4*>(&C[(size_t)(m0 + ty * TM + i) * N + n0 + tx * TN]) = cv;
    }
}

// C[M,N] = A * B, with A stored [M,K] row-major, B stored [K,N] row-major.
__global__ void sgemm_nn(const float* __restrict__ A, const float* __restrict__ B,
                         float* __restrict__ C, int M, int N, int K) {
    __shared__ float As[BK][BM];
    __shared__ float Bs[BK][BN];

    const int t = threadIdx.x;
    const int tx = t & 15;
    const int ty = t >> 4;
    const int m0 = blockIdx.y * BM;
    const int n0 = blockIdx.x * BN;

    // A tile load: 64 rows x 16 k. float4 along K, then transpose into As.
    const int ar_row = t >> 2;          // 0..63
    const int ar_kg  = (t & 3) << 2;    // 0,4,8,12

    // B tile load: 16 k x 64 n, float4 along N.
    const int lk = t >> 4;
    const int ln = (t & 15) << 2;

    float acc[TM][TN];
    #pragma unroll
    for (int i = 0; i < TM; i++)
        #pragma unroll
        for (int j = 0; j < TN; j++) acc[i][j] = 0.f;

    for (int k0 = 0; k0 < K; k0 += BK) {
        float4 av = *reinterpret_cast<const float4*>(&A[(size_t)(m0 + ar_row) * K + k0 + ar_kg]);
        As[ar_kg + 0][ar_row] = av.x;
        As[ar_kg + 1][ar_row] = av.y;
        As[ar_kg + 2][ar_row] = av.z;
        As[ar_kg + 3][ar_row] = av.w;

        float4 bv = *reinterpret_cast<const float4*>(&B[(size_t)(k0 + lk) * N + n0 + ln]);
        *reinterpret_cast<float4*>(&Bs[lk][ln]) = bv;
        __syncthreads();

        #pragma unroll
        for (int kk = 0; kk < BK; kk++) {
            float4 ar = *reinterpret_cast<float4*>(&As[kk][ty * TM]);
            float4 br = *reinterpret_cast<float4*>(&Bs[kk][tx * TN]);
            float a[TM] = {ar.x, ar.y, ar.z, ar.w};
            float b[TN] = {br.x, br.y, br.z, br.w};
            #pragma unroll
            for (int i = 0; i < TM; i++)
                #pragma unroll
                for (int j = 0; j < TN; j++)
                    acc[i][j] += a[i] * b[j];
        }
        __syncthreads();
    }

    #pragma unroll
    for (int i = 0; i < TM; i++) {
        float4 cv = make_float4(acc[i][0], acc[i][1], acc[i][2], acc[i][3]);
        *reinterpret_cast<float4*>(&C[(size_t)(m0 + ty * TM + i) * N + n0 + tx * TN]) = cv;
    }
}

// ---------------------------------------------------------------------------
extern "C" void kernel_launch(void* const* d_in, const int* in_sizes, int n_in,
                              void* d_out, int out_size) {
    const float* x = (const float*)d_in[0];        // [8192, 1024]
    const float* w = (const float*)d_in[1];        // [1024, 1024]
    float* out = (float*)d_out;                    // [8192, 1024]

    float* norm;
    float* G;
    float* H;
    cudaGetSymbolAddress((void**)&norm, g_norm);
    cudaGetSymbolAddress((void**)&G, g_G);
    cudaGetSymbolAddress((void**)&H, g_H);

    // 1) norm = row_l2_normalize(x)
    rownorm_kernel<<<NROWS, 256>>>(x, norm);

    // 2) G = norm^T @ x   [1024,1024], K=8192
    sgemm_tn<<<dim3(DIM / BN, DIM / BM), 256>>>(norm, x, G, DIM, DIM, NROWS);

    // 3) H = G @ W        [1024,1024], K=1024
    sgemm_nn<<<dim3(DIM / BN, DIM / BM), 256>>>(G, w, H, DIM, DIM, DIM);

    // 4) out = norm @ H   [8192,1024], K=1024
    sgemm_nn<<<dim3(DIM / BN, NROWS / BM), 256>>>(norm, H, out, NROWS, DIM, DIM);
}

// round 3
// speedup vs baseline: 2.5363x; 2.5363x over previous
#include <cuda_runtime.h>
#include <cuda_bf16.h>
#include <cstdint>

// out = norm @ ((norm^T @ x) @ W),  norm = x / max(||x_row||, 1e-12)
// GEMMs: bf16 hi/lo split (3 products) on mma.sync.m16n8k16 (HMMA path; tcgen05
// is unusable because the harness compiles via compute_103 PTX, which rejects it).

#define NROWS 8192
#define DIM   1024
typedef __nv_bfloat16 bf16;

// ---------------- scratch (device globals; no allocation allowed) ----------
__device__ float g_inv[NROWS];
__device__ bf16 g_nh[NROWS * DIM],  g_nl[NROWS * DIM];    // norm row-major
__device__ bf16 g_xth[DIM * NROWS], g_xtl[DIM * NROWS];   // x^T
__device__ bf16 g_nth[DIM * NROWS], g_ntl[DIM * NROWS];   // norm^T
__device__ bf16 g_wth[DIM * DIM],   g_wtl[DIM * DIM];     // W^T
__device__ bf16 g_gh[DIM * DIM],    g_gl[DIM * DIM];      // G
__device__ bf16 g_hth[DIM * DIM],   g_htl[DIM * DIM];     // H^T
__device__ float g_P0[DIM * DIM], g_P1[DIM * DIM];        // split-K partials

// ---------------- PTX helpers ----------------------------------------------
__device__ __forceinline__ uint32_t smem_u32(const void* p) {
    uint32_t a;
    asm("{ .reg .u64 t; cvta.to.shared.u64 t, %1; cvt.u32.u64 %0, t; }" : "=r"(a) : "l"(p));
    return a;
}

#define CP16(saddr, gptr) \
    asm volatile("cp.async.cg.shared.global [%0], [%1], 16;" :: "r"(saddr), "l"(gptr))
#define CP_COMMIT() asm volatile("cp.async.commit_group;" ::: "memory")
#define CP_WAIT(n)  asm volatile("cp.async.wait_group %0;" :: "n"(n) : "memory")

#define LDSM4(r, addr) \
    asm volatile("ldmatrix.sync.aligned.m8n8.x4.shared.b16 {%0,%1,%2,%3}, [%4];" \
        : "=r"((r)[0]), "=r"((r)[1]), "=r"((r)[2]), "=r"((r)[3]) : "r"(addr))

#define MMA(c, a, b) \
    asm volatile("mma.sync.aligned.m16n8k16.row.col.f32.bf16.bf16.f32 " \
        "{%0,%1,%2,%3}, {%4,%5,%6,%7}, {%8,%9}, {%0,%1,%2,%3};" \
        : "+f"((c)[0]), "+f"((c)[1]), "+f"((c)[2]), "+f"((c)[3]) \
        : "r"((a)[0]), "r"((a)[1]), "r"((a)[2]), "r"((a)[3]), "r"((b)[0]), "r"((b)[1]))

// ---------------- small kernels --------------------------------------------
__global__ void rownorm_inv(const float* __restrict__ x, float* __restrict__ inv) {
    const int row = blockIdx.x;
    float4 v = reinterpret_cast<const float4*>(x + (size_t)row * DIM)[threadIdx.x];
    float s = v.x * v.x + v.y * v.y + v.z * v.z + v.w * v.w;
    #pragma unroll
    for (int o = 16; o > 0; o >>= 1) s += __shfl_down_sync(0xFFFFFFFFu, s, o);
    __shared__ float ws[8];
    if ((threadIdx.x & 31) == 0) ws[threadIdx.x >> 5] = s;
    __syncthreads();
    if (threadIdx.x == 0) {
        float t = 0.f;
        #pragma unroll
        for (int i = 0; i < 8; i++) t += ws[i];
        inv[row] = 1.0f / fmaxf(sqrtf(t), 1e-12f);
    }
}

__device__ __forceinline__ void split_bf(float v, bf16& h, bf16& l) {
    h = __float2bfloat16_rn(v);
    l = __float2bfloat16_rn(v - __bfloat162float(h));
}

__global__ void conv_x(const float* __restrict__ x, const float* __restrict__ inv,
                       bf16* __restrict__ nh, bf16* __restrict__ nl,
                       bf16* __restrict__ xth, bf16* __restrict__ xtl,
                       bf16* __restrict__ nth, bf16* __restrict__ ntl) {
    __shared__ float sx[32][33];
    __shared__ float sn[32][33];
    const int c = blockIdx.x * 32 + threadIdx.x;
    const int r0 = blockIdx.y * 32;
    #pragma unroll
    for (int i = 0; i < 4; i++) {
        int rl = threadIdx.y + i * 8;
        int r = r0 + rl;
        float v = x[(size_t)r * DIM + c];
        float nv = v * inv[r];
        bf16 h, l;
        split_bf(nv, h, l);
        nh[(size_t)r * DIM + c] = h;
        nl[(size_t)r * DIM + c] = l;
        sx[rl][threadIdx.x] = v;
        sn[rl][threadIdx.x] = nv;
    }
    __syncthreads();
    const int tr = r0 + threadIdx.x;
    #pragma unroll
    for (int i = 0; i < 4; i++) {
        int cl = threadIdx.y + i * 8;
        int tc = blockIdx.x * 32 + cl;
        bf16 h, l;
        split_bf(sx[threadIdx.x][cl], h, l);
        xth[(size_t)tc * NROWS + tr] = h;
        xtl[(size_t)tc * NROWS + tr] = l;
        split_bf(sn[threadIdx.x][cl], h, l);
        nth[(size_t)tc * NROWS + tr] = h;
        ntl[(size_t)tc * NROWS + tr] = l;
    }
}

__global__ void conv_w(const float* __restrict__ w,
                       bf16* __restrict__ wth, bf16* __restrict__ wtl) {
    __shared__ float sw[32][33];
    const int c = blockIdx.x * 32 + threadIdx.x;
    const int r0 = blockIdx.y * 32;
    #pragma unroll
    for (int i = 0; i < 4; i++) {
        int rl = threadIdx.y + i * 8;
        sw[rl][threadIdx.x] = w[(size_t)(r0 + rl) * DIM + c];
    }
    __syncthreads();
    const int tr = r0 + threadIdx.x;
    #pragma unroll
    for (int i = 0; i < 4; i++) {
        int cl = threadIdx.y + i * 8;
        int tc = blockIdx.x * 32 + cl;
        bf16 h, l;
        split_bf(sw[threadIdx.x][cl], h, l);
        wth[(size_t)tc * DIM + tr] = h;
        wtl[(size_t)tc * DIM + tr] = l;
    }
}

// P = P0 + P1, then split into bf16 hi/lo
__global__ void combine_split(const float* __restrict__ P0, const float* __restrict__ P1,
                              bf16* __restrict__ hi, bf16* __restrict__ lo) {
    const int i = (blockIdx.x * 256 + threadIdx.x) * 4;
    float4 a = *reinterpret_cast<const float4*>(P0 + i);
    float4 b = *reinterpret_cast<const float4*>(P1 + i);
    float v[4] = {a.x + b.x, a.y + b.y, a.z + b.z, a.w + b.w};
    bf16 h[4], l[4];
    #pragma unroll
    for (int j = 0; j < 4; j++) split_bf(v[j], h[j], l[j]);
    *reinterpret_cast<uint2*>(hi + i) = *reinterpret_cast<uint2*>(h);
    *reinterpret_cast<uint2*>(lo + i) = *reinterpret_cast<uint2*>(l);
}

// ---------------- HMMA GEMM: C[m,n] = sum_k A[m,k]*B[n,k], hi/lo 3-product --
// CTA tile 128x128, BK=32, 8 warps (2m x 4n), warp tile 64x32.
// SMEM: 4 tiles (Ah, Al, Bh, Bl) of 128 rows x 32 bf16, padded row = 80B.
#define TILE_PB  10240                // 128 * 80
#define STAGE_B  (4 * TILE_PB)        // 40960
#define SMEM_DYN (2 * STAGE_B)        // 81920

__device__ __forceinline__ void stage_load(uint32_t s_stage,
                                           const bf16* __restrict__ Ah, const bf16* __restrict__ Al,
                                           const bf16* __restrict__ Bh, const bf16* __restrict__ Bl,
                                           int m0, int n0, int k, int ldk, int tid) {
    const int row = tid >> 1;
    const int cb = (tid & 1) * 32;        // 0 or 32 bytes within the 64B row
    const uint32_t so = s_stage + row * 80 + cb;
    const size_t goA = ((size_t)(m0 + row) * ldk + k) * 2 + cb;
    const size_t goB = ((size_t)(n0 + row) * ldk + k) * 2 + cb;
    const char* pAh = (const char*)Ah + goA;
    const char* pAl = (const char*)Al + goA;
    const char* pBh = (const char*)Bh + goB;
    const char* pBl = (const char*)Bl + goB;
    CP16(so,                     pAh); CP16(so + 16,                     pAh + 16);
    CP16(so + TILE_PB,           pAl); CP16(so + TILE_PB + 16,           pAl + 16);
    CP16(so + 2 * TILE_PB,       pBh); CP16(so + 2 * TILE_PB + 16,       pBh + 16);
    CP16(so + 3 * TILE_PB,       pBl); CP16(so + 3 * TILE_PB + 16,       pBl + 16);
}

__global__ __launch_bounds__(256, 1)
void gemm_hmma(const bf16* __restrict__ Ah, const bf16* __restrict__ Al,
               const bf16* __restrict__ Bh, const bf16* __restrict__ Bl,
               float* __restrict__ C0, float* __restrict__ C1,
               int N, int ldk, int ksplit) {
    extern __shared__ char smem[];
    const uint32_t su = smem_u32(smem);
    const int tid = threadIdx.x;
    const int lane = tid & 31;
    const int wid = tid >> 5;
    const int warp_m = wid & 1;     // 0..1 (64 rows each)
    const int warp_n = wid >> 1;    // 0..3 (32 cols each)
    const int m0 = blockIdx.y * 128, n0 = blockIdx.x * 128;
    const int k0 = blockIdx.z * ksplit;
    float* C = blockIdx.z ? C1 : C0;

    float acc[4][4][4];
    #pragma unroll
    for (int i = 0; i < 4; i++)
        #pragma unroll
        for (int j = 0; j < 4; j++)
            #pragma unroll
            for (int q = 0; q < 4; q++) acc[i][j][q] = 0.f;

    // ldmatrix lane addresses (byte offsets within a tile)
    const uint32_t a_off = (uint32_t)(warp_m * 64 + (lane & 15)) * 80 + ((lane >> 4) << 4);
    const uint32_t b_off = (uint32_t)(warp_n * 32 + ((lane >> 4) << 3) + (lane & 7)) * 80
                         + (((lane >> 3) & 1) << 4);

    const int NIT = ksplit / 32;
    stage_load(su, Ah, Al, Bh, Bl, m0, n0, k0, ldk, tid);
    CP_COMMIT();

    for (int it = 0; it < NIT; it++) {
        if (it + 1 < NIT) {
            stage_load(su + ((it + 1) & 1) * STAGE_B, Ah, Al, Bh, Bl,
                       m0, n0, k0 + (it + 1) * 32, ldk, tid);
            CP_COMMIT();
            CP_WAIT(1);
        } else {
            CP_WAIT(0);
        }
        __syncthreads();

        const uint32_t st = su + (it & 1) * STAGE_B;
        const uint32_t a_h = st + a_off;
        const uint32_t a_l = a_h + TILE_PB;
        const uint32_t b_h = st + 2 * TILE_PB + b_off;
        const uint32_t b_l = b_h + TILE_PB;

        #pragma unroll
        for (int ks = 0; ks < 2; ks++) {
            uint32_t ah[4][4], al[4][4], bh[4][2], bl[4][2];
            #pragma unroll
            for (int mf = 0; mf < 4; mf++) {
                LDSM4(ah[mf], a_h + mf * 1280 + ks * 32);
                LDSM4(al[mf], a_l + mf * 1280 + ks * 32);
            }
            #pragma unroll
            for (int bg = 0; bg < 2; bg++) {
                uint32_t t[4];
                LDSM4(t, b_h + bg * 1280 + ks * 32);
                bh[2 * bg][0] = t[0]; bh[2 * bg][1] = t[1];
                bh[2 * bg + 1][0] = t[2]; bh[2 * bg + 1][1] = t[3];
                LDSM4(t, b_l + bg * 1280 + ks * 32);
                bl[2 * bg][0] = t[0]; bl[2 * bg][1] = t[1];
                bl[2 * bg + 1][0] = t[2]; bl[2 * bg + 1][1] = t[3];
            }
            #pragma unroll
            for (int mf = 0; mf < 4; mf++)
                #pragma unroll
                for (int nf = 0; nf < 4; nf++) {
                    MMA(acc[mf][nf], ah[mf], bh[nf]);
                    MMA(acc[mf][nf], ah[mf], bl[nf]);
                    MMA(acc[mf][nf], al[mf], bh[nf]);
                }
        }
        __syncthreads();
    }

    // epilogue: fp32 C
    const int g = lane >> 2, t4 = lane & 3;
    #pragma unroll
    for (int mf = 0; mf < 4; mf++) {
        const int r = m0 + warp_m * 64 + mf * 16 + g;
        #pragma unroll
        for (int nf = 0; nf < 4; nf++) {
            const int c = n0 + warp_n * 32 + nf * 8 + t4 * 2;
            float2 v0 = make_float2(acc[mf][nf][0], acc[mf][nf][1]);
            float2 v1 = make_float2(acc[mf][nf][2], acc[mf][nf][3]);
            *reinterpret_cast<float2*>(C + (size_t)r * N + c) = v0;
            *reinterpret_cast<float2*>(C + (size_t)(r + 8) * N + c) = v1;
        }
    }
}

// ---------------------------------------------------------------------------
extern "C" void kernel_launch(void* const* d_in, const int* in_sizes, int n_in,
                              void* d_out, int out_size) {
    const float* x = (const float*)d_in[0];
    const float* w = (const float*)d_in[1];
    float* out = (float*)d_out;

    float *inv, *P0, *P1;
    cudaGetSymbolAddress((void**)&inv, g_inv);
    cudaGetSymbolAddress((void**)&P0, g_P0);
    cudaGetSymbolAddress((void**)&P1, g_P1);
    bf16 *nh, *nl, *xth, *xtl, *nth, *ntl, *wth, *wtl, *gh, *gl, *hth, *htl;
    cudaGetSymbolAddress((void**)&nh, g_nh);   cudaGetSymbolAddress((void**)&nl, g_nl);
    cudaGetSymbolAddress((void**)&xth, g_xth); cudaGetSymbolAddress((void**)&xtl, g_xtl);
    cudaGetSymbolAddress((void**)&nth, g_nth); cudaGetSymbolAddress((void**)&ntl, g_ntl);
    cudaGetSymbolAddress((void**)&wth, g_wth); cudaGetSymbolAddress((void**)&wtl, g_wtl);
    cudaGetSymbolAddress((void**)&gh, g_gh);   cudaGetSymbolAddress((void**)&gl, g_gl);
    cudaGetSymbolAddress((void**)&hth, g_hth); cudaGetSymbolAddress((void**)&htl, g_htl);

    cudaFuncSetAttribute(gemm_hmma, cudaFuncAttributeMaxDynamicSharedMemorySize, SMEM_DYN);

    rownorm_inv<<<NROWS, 256>>>(x, inv);
    conv_x<<<dim3(DIM / 32, NROWS / 32), dim3(32, 8)>>>(x, inv, nh, nl, xth, xtl, nth, ntl);
    conv_w<<<dim3(DIM / 32, DIM / 32), dim3(32, 8)>>>(w, wth, wtl);

    // G = norm^T @ x : A=nT, B=xT, M=N=1024, K=8192, split-K=2
    gemm_hmma<<<dim3(8, 8, 2), 256, SMEM_DYN>>>(nth, ntl, xth, xtl, P0, P1, DIM, NROWS, NROWS / 2);
    combine_split<<<DIM * DIM / 1024, 256>>>(P0, P1, gh, gl);

    // H^T = MM(W^T, G) : M=N=1024, K=1024, split-K=2
    gemm_hmma<<<dim3(8, 8, 2), 256, SMEM_DYN>>>(wth, wtl, gh, gl, P0, P1, DIM, DIM, DIM / 2);
    combine_split<<<DIM * DIM / 1024, 256>>>(P0, P1, hth, htl);

    // out = MM(norm, H^T) : M=8192, N=1024, K=1024
    gemm_hmma<<<dim3(8, 64, 1), 256, SMEM_DYN>>>(nh, nl, hth, htl, out, out, DIM, DIM, DIM);
}

// round 4
// speedup vs baseline: 3.1182x; 1.2294x over previous
#include <cuda_runtime.h>
#include <cuda_bf16.h>
#include <cstdint>

// out = norm @ ((norm^T @ x) @ W),  norm = x / max(||x_row||, 1e-12)
// G = norm^T @ x is SYMMETRIC (G_ij = sum_r inv_r x_ri x_rj) -> triangle-only GEMM1.
// GEMMs: bf16 hi/lo split (3 products) on mma.sync.m16n8k16, 2 CTAs/SM.

#define NROWS 8192
#define DIM   1024
typedef __nv_bfloat16 bf16;

// ---------------- scratch (device globals; no allocation allowed) ----------
__device__ float g_inv[NROWS];
__device__ bf16 g_nh[NROWS * DIM],  g_nl[NROWS * DIM];    // norm row-major
__device__ bf16 g_xth[DIM * NROWS], g_xtl[DIM * NROWS];   // x^T
__device__ bf16 g_nth[DIM * NROWS], g_ntl[DIM * NROWS];   // norm^T
__device__ bf16 g_wth[DIM * DIM],   g_wtl[DIM * DIM];     // W^T
__device__ bf16 g_gh[DIM * DIM],    g_gl[DIM * DIM];      // G
__device__ bf16 g_hth[DIM * DIM],   g_htl[DIM * DIM];     // H^T
__device__ float g_P[4 * DIM * DIM];                      // split-K partials

// 36 upper-triangle block pairs (bm >= bn) for an 8x8 block grid
__constant__ int2 c_tri[36] = {
    {0,0},{1,0},{1,1},{2,0},{2,1},{2,2},{3,0},{3,1},{3,2},{3,3},
    {4,0},{4,1},{4,2},{4,3},{4,4},{5,0},{5,1},{5,2},{5,3},{5,4},
    {5,5},{6,0},{6,1},{6,2},{6,3},{6,4},{6,5},{6,6},{7,0},{7,1},
    {7,2},{7,3},{7,4},{7,5},{7,6},{7,7}
};

// ---------------- PTX helpers ----------------------------------------------
__device__ __forceinline__ uint32_t smem_u32(const void* p) {
    uint32_t a;
    asm("{ .reg .u64 t; cvta.to.shared.u64 t, %1; cvt.u32.u64 %0, t; }" : "=r"(a) : "l"(p));
    return a;
}

#define CP16(saddr, gptr) \
    asm volatile("cp.async.cg.shared.global [%0], [%1], 16;" :: "r"(saddr), "l"(gptr))
#define CP_COMMIT() asm volatile("cp.async.commit_group;" ::: "memory")
#define CP_WAIT(n)  asm volatile("cp.async.wait_group %0;" :: "n"(n) : "memory")

#define LDSM4(r, addr) \
    asm volatile("ldmatrix.sync.aligned.m8n8.x4.shared.b16 {%0,%1,%2,%3}, [%4];" \
        : "=r"((r)[0]), "=r"((r)[1]), "=r"((r)[2]), "=r"((r)[3]) : "r"(addr))

#define MMA(c, a, b) \
    asm volatile("mma.sync.aligned.m16n8k16.row.col.f32.bf16.bf16.f32 " \
        "{%0,%1,%2,%3}, {%4,%5,%6,%7}, {%8,%9}, {%0,%1,%2,%3};" \
        : "+f"((c)[0]), "+f"((c)[1]), "+f"((c)[2]), "+f"((c)[3]) \
        : "r"((a)[0]), "r"((a)[1]), "r"((a)[2]), "r"((a)[3]), "r"((b)[0]), "r"((b)[1]))

// ---------------- small kernels --------------------------------------------
__global__ void rownorm_inv(const float* __restrict__ x, float* __restrict__ inv) {
    const int row = blockIdx.x;
    float4 v = reinterpret_cast<const float4*>(x + (size_t)row * DIM)[threadIdx.x];
    float s = v.x * v.x + v.y * v.y + v.z * v.z + v.w * v.w;
    #pragma unroll
    for (int o = 16; o > 0; o >>= 1) s += __shfl_down_sync(0xFFFFFFFFu, s, o);
    __shared__ float ws[8];
    if ((threadIdx.x & 31) == 0) ws[threadIdx.x >> 5] = s;
    __syncthreads();
    if (threadIdx.x == 0) {
        float t = 0.f;
        #pragma unroll
        for (int i = 0; i < 8; i++) t += ws[i];
        inv[row] = 1.0f / fmaxf(sqrtf(t), 1e-12f);
    }
}

__device__ __forceinline__ void split_bf(float v, bf16& h, bf16& l) {
    h = __float2bfloat16_rn(v);
    l = __float2bfloat16_rn(v - __bfloat162float(h));
}

__global__ void conv_x(const float* __restrict__ x, const float* __restrict__ inv,
                       bf16* __restrict__ nh, bf16* __restrict__ nl,
                       bf16* __restrict__ xth, bf16* __restrict__ xtl,
                       bf16* __restrict__ nth, bf16* __restrict__ ntl) {
    __shared__ float sx[32][33];
    __shared__ float sn[32][33];
    const int c = blockIdx.x * 32 + threadIdx.x;
    const int r0 = blockIdx.y * 32;
    #pragma unroll
    for (int i = 0; i < 4; i++) {
        int rl = threadIdx.y + i * 8;
        int r = r0 + rl;
        float v = x[(size_t)r * DIM + c];
        float nv = v * inv[r];
        bf16 h, l;
        split_bf(nv, h, l);
        nh[(size_t)r * DIM + c] = h;
        nl[(size_t)r * DIM + c] = l;
        sx[rl][threadIdx.x] = v;
        sn[rl][threadIdx.x] = nv;
    }
    __syncthreads();
    const int tr = r0 + threadIdx.x;
    #pragma unroll
    for (int i = 0; i < 4; i++) {
        int cl = threadIdx.y + i * 8;
        int tc = blockIdx.x * 32 + cl;
        bf16 h, l;
        split_bf(sx[threadIdx.x][cl], h, l);
        xth[(size_t)tc * NROWS + tr] = h;
        xtl[(size_t)tc * NROWS + tr] = l;
        split_bf(sn[threadIdx.x][cl], h, l);
        nth[(size_t)tc * NROWS + tr] = h;
        ntl[(size_t)tc * NROWS + tr] = l;
    }
}

__global__ void conv_w(const float* __restrict__ w,
                       bf16* __restrict__ wth, bf16* __restrict__ wtl) {
    __shared__ float sw[32][33];
    const int c = blockIdx.x * 32 + threadIdx.x;
    const int r0 = blockIdx.y * 32;
    #pragma unroll
    for (int i = 0; i < 4; i++) {
        int rl = threadIdx.y + i * 8;
        sw[rl][threadIdx.x] = w[(size_t)(r0 + rl) * DIM + c];
    }
    __syncthreads();
    const int tr = r0 + threadIdx.x;
    #pragma unroll
    for (int i = 0; i < 4; i++) {
        int cl = threadIdx.y + i * 8;
        int tc = blockIdx.x * 32 + cl;
        bf16 h, l;
        split_bf(sw[threadIdx.x][cl], h, l);
        wth[(size_t)tc * DIM + tr] = h;
        wtl[(size_t)tc * DIM + tr] = l;
    }
}

// sum 4 split-K partials of a triangle block, split to bf16 hi/lo, mirror.
__global__ void combine4_mirror(const float* __restrict__ P,
                                bf16* __restrict__ hi, bf16* __restrict__ lo) {
    const int2 bp = c_tri[blockIdx.y];
    const int idx = (blockIdx.x * 256 + threadIdx.x) * 4;  // 0..16383 within block
    const int r = idx >> 7;
    const int c = idx & 127;
    const int R = bp.x * 128 + r;
    const int C = bp.y * 128 + c;
    const size_t o = (size_t)R * DIM + C;
    float4 a = *reinterpret_cast<const float4*>(P + o);
    float4 b = *reinterpret_cast<const float4*>(P + DIM * DIM + o);
    float4 d = *reinterpret_cast<const float4*>(P + 2 * DIM * DIM + o);
    float4 e = *reinterpret_cast<const float4*>(P + 3 * DIM * DIM + o);
    float v[4] = {a.x + b.x + d.x + e.x, a.y + b.y + d.y + e.y,
                  a.z + b.z + d.z + e.z, a.w + b.w + d.w + e.w};
    bf16 h[4], l[4];
    #pragma unroll
    for (int j = 0; j < 4; j++) split_bf(v[j], h[j], l[j]);
    *reinterpret_cast<uint2*>(hi + o) = *reinterpret_cast<const uint2*>(h);
    *reinterpret_cast<uint2*>(lo + o) = *reinterpret_cast<const uint2*>(l);
    if (bp.x != bp.y) {  // mirror (G symmetric)
        #pragma unroll
        for (int j = 0; j < 4; j++) {
            hi[(size_t)(C + j) * DIM + R] = h[j];
            lo[(size_t)(C + j) * DIM + R] = l[j];
        }
    }
}

// sum 2 split-K partials, split to bf16 hi/lo
__global__ void combine2(const float* __restrict__ P,
                         bf16* __restrict__ hi, bf16* __restrict__ lo) {
    const int i = (blockIdx.x * 256 + threadIdx.x) * 4;
    float4 a = *reinterpret_cast<const float4*>(P + i);
    float4 b = *reinterpret_cast<const float4*>(P + DIM * DIM + i);
    float v[4] = {a.x + b.x, a.y + b.y, a.z + b.z, a.w + b.w};
    bf16 h[4], l[4];
    #pragma unroll
    for (int j = 0; j < 4; j++) split_bf(v[j], h[j], l[j]);
    *reinterpret_cast<uint2*>(hi + i) = *reinterpret_cast<const uint2*>(h);
    *reinterpret_cast<uint2*>(lo + i) = *reinterpret_cast<const uint2*>(l);
}

// ---------------- HMMA GEMM: C[m,n] = sum_k A[m,k]*B[n,k], hi/lo 3-product --
#define TILE_PB  10240                // 128 * 80
#define STAGE_B  (4 * TILE_PB)        // 40960
#define SMEM_DYN (2 * STAGE_B)        // 81920

__device__ __forceinline__ void stage_load(uint32_t s_stage,
                                           const bf16* __restrict__ Ah, const bf16* __restrict__ Al,
                                           const bf16* __restrict__ Bh, const bf16* __restrict__ Bl,
                                           int m0, int n0, int k, int ldk, int tid) {
    const int row = tid >> 1;
    const int cb = (tid & 1) * 32;
    const uint32_t so = s_stage + row * 80 + cb;
    const size_t goA = ((size_t)(m0 + row) * ldk + k) * 2 + cb;
    const size_t goB = ((size_t)(n0 + row) * ldk + k) * 2 + cb;
    const char* pAh = (const char*)Ah + goA;
    const char* pAl = (const char*)Al + goA;
    const char* pBh = (const char*)Bh + goB;
    const char* pBl = (const char*)Bl + goB;
    CP16(so,                     pAh); CP16(so + 16,                     pAh + 16);
    CP16(so + TILE_PB,           pAl); CP16(so + TILE_PB + 16,           pAl + 16);
    CP16(so + 2 * TILE_PB,       pBh); CP16(so + 2 * TILE_PB + 16,       pBh + 16);
    CP16(so + 3 * TILE_PB,       pBl); CP16(so + 3 * TILE_PB + 16,       pBl + 16);
}

template <int TRI>
__global__ __launch_bounds__(256, 2)
void gemm_hmma(const bf16* __restrict__ Ah, const bf16* __restrict__ Al,
               const bf16* __restrict__ Bh, const bf16* __restrict__ Bl,
               float* __restrict__ Cbase, size_t cplane,
               int N, int ldk, int ksplit) {
    extern __shared__ char smem[];
    const uint32_t su = smem_u32(smem);
    const int tid = threadIdx.x;
    const int lane = tid & 31;
    const int wid = tid >> 5;
    const int warp_m = wid & 1;
    const int warp_n = wid >> 1;
    int m0, n0;
    if (TRI) {
        const int2 bp = c_tri[blockIdx.x];
        m0 = bp.x * 128; n0 = bp.y * 128;
    } else {
        m0 = blockIdx.y * 128; n0 = blockIdx.x * 128;
    }
    const int k0 = blockIdx.z * ksplit;
    float* C = Cbase + (size_t)blockIdx.z * cplane;

    float acc[4][4][4];
    #pragma unroll
    for (int i = 0; i < 4; i++)
        #pragma unroll
        for (int j = 0; j < 4; j++)
            #pragma unroll
            for (int q = 0; q < 4; q++) acc[i][j][q] = 0.f;

    const uint32_t a_off = (uint32_t)(warp_m * 64 + (lane & 15)) * 80 + ((lane >> 4) << 4);
    const uint32_t b_off = (uint32_t)(warp_n * 32 + ((lane >> 4) << 3) + (lane & 7)) * 80
                         + (((lane >> 3) & 1) << 4);

    const int NIT = ksplit / 32;
    stage_load(su, Ah, Al, Bh, Bl, m0, n0, k0, ldk, tid);
    CP_COMMIT();

    for (int it = 0; it < NIT; it++) {
        if (it + 1 < NIT) {
            stage_load(su + ((it + 1) & 1) * STAGE_B, Ah, Al, Bh, Bl,
                       m0, n0, k0 + (it + 1) * 32, ldk, tid);
            CP_COMMIT();
            CP_WAIT(1);
        } else {
            CP_WAIT(0);
        }
        __syncthreads();

        const uint32_t st = su + (it & 1) * STAGE_B;
        const uint32_t a_h = st + a_off;
        const uint32_t a_l = a_h + TILE_PB;
        const uint32_t b_h = st + 2 * TILE_PB + b_off;
        const uint32_t b_l = b_h + TILE_PB;

        #pragma unroll
        for (int ks = 0; ks < 2; ks++) {
            uint32_t ah[4][4], al[4][4], bh[4][2], bl[4][2];
            #pragma unroll
            for (int mf = 0; mf < 4; mf++) {
                LDSM4(ah[mf], a_h + mf * 1280 + ks * 32);
                LDSM4(al[mf], a_l + mf * 1280 + ks * 32);
            }
            #pragma unroll
            for (int bg = 0; bg < 2; bg++) {
                uint32_t t[4];
                LDSM4(t, b_h + bg * 1280 + ks * 32);
                bh[2 * bg][0] = t[0]; bh[2 * bg][1] = t[1];
                bh[2 * bg + 1][0] = t[2]; bh[2 * bg + 1][1] = t[3];
                LDSM4(t, b_l + bg * 1280 + ks * 32);
                bl[2 * bg][0] = t[0]; bl[2 * bg][1] = t[1];
                bl[2 * bg + 1][0] = t[2]; bl[2 * bg + 1][1] = t[3];
            }
            #pragma unroll
            for (int mf = 0; mf < 4; mf++)
                #pragma unroll
                for (int nf = 0; nf < 4; nf++) {
                    MMA(acc[mf][nf], ah[mf], bh[nf]);
                    MMA(acc[mf][nf], ah[mf], bl[nf]);
                    MMA(acc[mf][nf], al[mf], bh[nf]);
                }
        }
        __syncthreads();
    }

    const int g = lane >> 2, t4 = lane & 3;
    #pragma unroll
    for (int mf = 0; mf < 4; mf++) {
        const int r = m0 + warp_m * 64 + mf * 16 + g;
        #pragma unroll
        for (int nf = 0; nf < 4; nf++) {
            const int c = n0 + warp_n * 32 + nf * 8 + t4 * 2;
            float2 v0 = make_float2(acc[mf][nf][0], acc[mf][nf][1]);
            float2 v1 = make_float2(acc[mf][nf][2], acc[mf][nf][3]);
            *reinterpret_cast<float2*>(C + (size_t)r * N + c) = v0;
            *reinterpret_cast<float2*>(C + (size_t)(r + 8) * N + c) = v1;
        }
    }
}

// ---------------------------------------------------------------------------
extern "C" void kernel_launch(void* const* d_in, const int* in_sizes, int n_in,
                              void* d_out, int out_size) {
    const float* x = (const float*)d_in[0];
    const float* w = (const float*)d_in[1];
    float* out = (float*)d_out;

    float *inv, *P;
    cudaGetSymbolAddress((void**)&inv, g_inv);
    cudaGetSymbolAddress((void**)&P, g_P);
    bf16 *nh, *nl, *xth, *xtl, *nth, *ntl, *wth, *wtl, *gh, *gl, *hth, *htl;
    cudaGetSymbolAddress((void**)&nh, g_nh);   cudaGetSymbolAddress((void**)&nl, g_nl);
    cudaGetSymbolAddress((void**)&xth, g_xth); cudaGetSymbolAddress((void**)&xtl, g_xtl);
    cudaGetSymbolAddress((void**)&nth, g_nth); cudaGetSymbolAddress((void**)&ntl, g_ntl);
    cudaGetSymbolAddress((void**)&wth, g_wth); cudaGetSymbolAddress((void**)&wtl, g_wtl);
    cudaGetSymbolAddress((void**)&gh, g_gh);   cudaGetSymbolAddress((void**)&gl, g_gl);
    cudaGetSymbolAddress((void**)&hth, g_hth); cudaGetSymbolAddress((void**)&htl, g_htl);

    cudaFuncSetAttribute(gemm_hmma<0>, cudaFuncAttributeMaxDynamicSharedMemorySize, SMEM_DYN);
    cudaFuncSetAttribute(gemm_hmma<1>, cudaFuncAttributeMaxDynamicSharedMemorySize, SMEM_DYN);

    rownorm_inv<<<NROWS, 256>>>(x, inv);
    conv_x<<<dim3(DIM / 32, NROWS / 32), dim3(32, 8)>>>(x, inv, nh, nl, xth, xtl, nth, ntl);
    conv_w<<<dim3(DIM / 32, DIM / 32), dim3(32, 8)>>>(w, wth, wtl);

    // G = norm^T @ x (symmetric): triangle blocks only, split-K=4 (36*4=144 CTAs)
    gemm_hmma<1><<<dim3(36, 1, 4), 256, SMEM_DYN>>>(
        nth, ntl, xth, xtl, P, (size_t)DIM * DIM, DIM, NROWS, NROWS / 4);
    combine4_mirror<<<dim3(16, 36), 256>>>(P, gh, gl);

    // H^T = MM(W^T, G) : M=N=1024, K=1024, split-K=2
    gemm_hmma<0><<<dim3(8, 8, 2), 256, SMEM_DYN>>>(
        wth, wtl, gh, gl, P, (size_t)DIM * DIM, DIM, DIM, DIM / 2);
    combine2<<<DIM * DIM / 1024, 256>>>(P, hth, htl);

    // out = MM(norm, H^T) : M=8192, N=1024, K=1024
    gemm_hmma<0><<<dim3(8, 64, 1), 256, SMEM_DYN>>>(
        nh, nl, hth, htl, out, 0, DIM, DIM, DIM);
}

// round 5
// speedup vs baseline: 3.2111x; 1.0298x over previous
#include <cuda_runtime.h>
#include <cuda_bf16.h>
#include <cstdint>

// out = norm @ ((norm^T @ x) @ W),  norm = x / max(||x_row||, 1e-12)
// y = sqrt(inv)*x  =>  G = y^T @ y (symmetric, one operand).
// GEMMs: bf16 hi/lo split (3 products) on mma.sync.m16n8k16.

#define NROWS 8192
#define DIM   1024
typedef __nv_bfloat16 bf16;

// ---------------- scratch (device globals; no allocation allowed) ----------
__device__ float g_inv[NROWS];
__device__ bf16 g_nh[NROWS * DIM],  g_nl[NROWS * DIM];    // norm row-major
__device__ bf16 g_yth[DIM * NROWS], g_ytl[DIM * NROWS];   // y^T  [1024,8192]
__device__ bf16 g_wth[DIM * DIM],   g_wtl[DIM * DIM];     // W^T
__device__ bf16 g_gh[DIM * DIM],    g_gl[DIM * DIM];      // G
__device__ bf16 g_hth[DIM * DIM],   g_htl[DIM * DIM];     // H^T
__device__ float g_P[8 * DIM * DIM];                      // split-K partials (8 planes)

// 36 upper-triangle block pairs (bm >= bn) for an 8x8 block grid
__constant__ int2 c_tri[36] = {
    {0,0},{1,0},{1,1},{2,0},{2,1},{2,2},{3,0},{3,1},{3,2},{3,3},
    {4,0},{4,1},{4,2},{4,3},{4,4},{5,0},{5,1},{5,2},{5,3},{5,4},
    {5,5},{6,0},{6,1},{6,2},{6,3},{6,4},{6,5},{6,6},{7,0},{7,1},
    {7,2},{7,3},{7,4},{7,5},{7,6},{7,7}
};

// ---------------- PTX helpers ----------------------------------------------
__device__ __forceinline__ uint32_t smem_u32(const void* p) {
    uint32_t a;
    asm("{ .reg .u64 t; cvta.to.shared.u64 t, %1; cvt.u32.u64 %0, t; }" : "=r"(a) : "l"(p));
    return a;
}

#define CP16(saddr, gptr) \
    asm volatile("cp.async.cg.shared.global [%0], [%1], 16;" :: "r"(saddr), "l"(gptr))
#define CP_COMMIT() asm volatile("cp.async.commit_group;" ::: "memory")
#define CP_WAIT(n)  asm volatile("cp.async.wait_group %0;" :: "n"(n) : "memory")

#define LDSM4(r, addr) \
    asm volatile("ldmatrix.sync.aligned.m8n8.x4.shared.b16 {%0,%1,%2,%3}, [%4];" \
        : "=r"((r)[0]), "=r"((r)[1]), "=r"((r)[2]), "=r"((r)[3]) : "r"(addr))

#define MMA(c, a, b) \
    asm volatile("mma.sync.aligned.m16n8k16.row.col.f32.bf16.bf16.f32 " \
        "{%0,%1,%2,%3}, {%4,%5,%6,%7}, {%8,%9}, {%0,%1,%2,%3};" \
        : "+f"((c)[0]), "+f"((c)[1]), "+f"((c)[2]), "+f"((c)[3]) \
        : "r"((a)[0]), "r"((a)[1]), "r"((a)[2]), "r"((a)[3]), "r"((b)[0]), "r"((b)[1]))

// ---------------- small kernels --------------------------------------------
__global__ void rownorm_inv(const float* __restrict__ x, float* __restrict__ inv) {
    const int row = blockIdx.x;
    float4 v = reinterpret_cast<const float4*>(x + (size_t)row * DIM)[threadIdx.x];
    float s = v.x * v.x + v.y * v.y + v.z * v.z + v.w * v.w;
    #pragma unroll
    for (int o = 16; o > 0; o >>= 1) s += __shfl_down_sync(0xFFFFFFFFu, s, o);
    __shared__ float ws[8];
    if ((threadIdx.x & 31) == 0) ws[threadIdx.x >> 5] = s;
    __syncthreads();
    if (threadIdx.x == 0) {
        float t = 0.f;
        #pragma unroll
        for (int i = 0; i < 8; i++) t += ws[i];
        inv[row] = 1.0f / fmaxf(sqrtf(t), 1e-12f);
    }
}

__device__ __forceinline__ void split_bf(float v, bf16& h, bf16& l) {
    h = __float2bfloat16_rn(v);
    l = __float2bfloat16_rn(v - __bfloat162float(h));
}

// x -> norm hi/lo (row-major), y^T hi/lo (K-major), y = sqrt(inv)*x
__global__ void conv_x(const float* __restrict__ x, const float* __restrict__ inv,
                       bf16* __restrict__ nh, bf16* __restrict__ nl,
                       bf16* __restrict__ yth, bf16* __restrict__ ytl) {
    __shared__ float sy[32][33];
    const int c = blockIdx.x * 32 + threadIdx.x;
    const int r0 = blockIdx.y * 32;
    #pragma unroll
    for (int i = 0; i < 4; i++) {
        int rl = threadIdx.y + i * 8;
        int r = r0 + rl;
        float iv = inv[r];
        float v = x[(size_t)r * DIM + c];
        float nv = v * iv;
        bf16 h, l;
        split_bf(nv, h, l);
        nh[(size_t)r * DIM + c] = h;
        nl[(size_t)r * DIM + c] = l;
        sy[rl][threadIdx.x] = v * sqrtf(iv);
    }
    __syncthreads();
    const int tr = r0 + threadIdx.x;
    #pragma unroll
    for (int i = 0; i < 4; i++) {
        int cl = threadIdx.y + i * 8;
        int tc = blockIdx.x * 32 + cl;
        bf16 h, l;
        split_bf(sy[threadIdx.x][cl], h, l);
        yth[(size_t)tc * NROWS + tr] = h;
        ytl[(size_t)tc * NROWS + tr] = l;
    }
}

__global__ void conv_w(const float* __restrict__ w,
                       bf16* __restrict__ wth, bf16* __restrict__ wtl) {
    __shared__ float sw[32][33];
    const int c = blockIdx.x * 32 + threadIdx.x;
    const int r0 = blockIdx.y * 32;
    #pragma unroll
    for (int i = 0; i < 4; i++) {
        int rl = threadIdx.y + i * 8;
        sw[rl][threadIdx.x] = w[(size_t)(r0 + rl) * DIM + c];
    }
    __syncthreads();
    const int tr = r0 + threadIdx.x;
    #pragma unroll
    for (int i = 0; i < 4; i++) {
        int cl = threadIdx.y + i * 8;
        int tc = blockIdx.x * 32 + cl;
        bf16 h, l;
        split_bf(sw[threadIdx.x][cl], h, l);
        wth[(size_t)tc * DIM + tr] = h;
        wtl[(size_t)tc * DIM + tr] = l;
    }
}

// sum NP split-K partials of a triangle block, split to bf16 hi/lo, mirror.
__global__ void combine_tri(const float* __restrict__ P, int np,
                            bf16* __restrict__ hi, bf16* __restrict__ lo) {
    const int2 bp = c_tri[blockIdx.y];
    const int idx = (blockIdx.x * 256 + threadIdx.x) * 4;
    const int R = bp.x * 128 + (idx >> 7);
    const int C = bp.y * 128 + (idx & 127);
    const size_t o = (size_t)R * DIM + C;
    float v[4] = {0.f, 0.f, 0.f, 0.f};
    for (int p = 0; p < np; p++) {
        float4 a = *reinterpret_cast<const float4*>(P + (size_t)p * DIM * DIM + o);
        v[0] += a.x; v[1] += a.y; v[2] += a.z; v[3] += a.w;
    }
    bf16 h[4], l[4];
    #pragma unroll
    for (int j = 0; j < 4; j++) split_bf(v[j], h[j], l[j]);
    *reinterpret_cast<uint2*>(hi + o) = *reinterpret_cast<const uint2*>(h);
    *reinterpret_cast<uint2*>(lo + o) = *reinterpret_cast<const uint2*>(l);
    if (bp.x != bp.y) {
        #pragma unroll
        for (int j = 0; j < 4; j++) {
            hi[(size_t)(C + j) * DIM + R] = h[j];
            lo[(size_t)(C + j) * DIM + R] = l[j];
        }
    }
}

// sum NP split-K partials (linear), split to bf16 hi/lo
__global__ void combine_lin(const float* __restrict__ P, int np,
                            bf16* __restrict__ hi, bf16* __restrict__ lo) {
    const int i = (blockIdx.x * 256 + threadIdx.x) * 4;
    float v[4] = {0.f, 0.f, 0.f, 0.f};
    for (int p = 0; p < np; p++) {
        float4 a = *reinterpret_cast<const float4*>(P + (size_t)p * DIM * DIM + i);
        v[0] += a.x; v[1] += a.y; v[2] += a.z; v[3] += a.w;
    }
    bf16 h[4], l[4];
    #pragma unroll
    for (int j = 0; j < 4; j++) split_bf(v[j], h[j], l[j]);
    *reinterpret_cast<uint2*>(hi + i) = *reinterpret_cast<const uint2*>(h);
    *reinterpret_cast<uint2*>(lo + i) = *reinterpret_cast<const uint2*>(l);
}

// ---------------- HMMA GEMM: C[m,n] = sum_k A[m,k]*B[n,k], hi/lo 3-product --
#define TILE_PB  10240                // 128 * 80
#define STAGE_B  (4 * TILE_PB)        // 40960
#define SMEM_DYN (2 * STAGE_B)        // 81920

__device__ __forceinline__ void stage_load(uint32_t s_stage,
                                           const bf16* __restrict__ Ah, const bf16* __restrict__ Al,
                                           const bf16* __restrict__ Bh, const bf16* __restrict__ Bl,
                                           int m0, int n0, int k, int ldk, int tid) {
    const int row = tid >> 1;
    const int cb = (tid & 1) * 32;
    const uint32_t so = s_stage + row * 80 + cb;
    const size_t goA = ((size_t)(m0 + row) * ldk + k) * 2 + cb;
    const size_t goB = ((size_t)(n0 + row) * ldk + k) * 2 + cb;
    const char* pAh = (const char*)Ah + goA;
    const char* pAl = (const char*)Al + goA;
    const char* pBh = (const char*)Bh + goB;
    const char* pBl = (const char*)Bl + goB;
    CP16(so,                     pAh); CP16(so + 16,                     pAh + 16);
    CP16(so + TILE_PB,           pAl); CP16(so + TILE_PB + 16,           pAl + 16);
    CP16(so + 2 * TILE_PB,       pBh); CP16(so + 2 * TILE_PB + 16,       pBh + 16);
    CP16(so + 3 * TILE_PB,       pBl); CP16(so + 3 * TILE_PB + 16,       pBl + 16);
}

template <int TRI>
__global__ __launch_bounds__(256, 2)
void gemm_hmma(const bf16* __restrict__ Ah, const bf16* __restrict__ Al,
               const bf16* __restrict__ Bh, const bf16* __restrict__ Bl,
               float* __restrict__ Cbase, size_t cplane,
               int N, int ldk, int ksplit) {
    extern __shared__ char smem[];
    const uint32_t su = smem_u32(smem);
    const int tid = threadIdx.x;
    const int lane = tid & 31;
    const int wid = tid >> 5;
    const int warp_m = wid & 1;
    const int warp_n = wid >> 1;
    int m0, n0;
    if (TRI) {
        const int2 bp = c_tri[blockIdx.x];
        m0 = bp.x * 128; n0 = bp.y * 128;
    } else {
        m0 = blockIdx.y * 128; n0 = blockIdx.x * 128;
    }
    const int k0 = blockIdx.z * ksplit;
    float* C = Cbase + (size_t)blockIdx.z * cplane;

    float acc[4][4][4];
    #pragma unroll
    for (int i = 0; i < 4; i++)
        #pragma unroll
        for (int j = 0; j < 4; j++)
            #pragma unroll
            for (int q = 0; q < 4; q++) acc[i][j][q] = 0.f;

    const uint32_t a_off = (uint32_t)(warp_m * 64 + (lane & 15)) * 80 + ((lane >> 4) << 4);
    const uint32_t b_off = (uint32_t)(warp_n * 32 + ((lane >> 4) << 3) + (lane & 7)) * 80
                         + (((lane >> 3) & 1) << 4);

    const int NIT = ksplit / 32;
    stage_load(su, Ah, Al, Bh, Bl, m0, n0, k0, ldk, tid);
    CP_COMMIT();

    for (int it = 0; it < NIT; it++) {
        if (it + 1 < NIT) {
            stage_load(su + ((it + 1) & 1) * STAGE_B, Ah, Al, Bh, Bl,
                       m0, n0, k0 + (it + 1) * 32, ldk, tid);
            CP_COMMIT();
            CP_WAIT(1);
        } else {
            CP_WAIT(0);
        }
        __syncthreads();

        const uint32_t st = su + (it & 1) * STAGE_B;
        const uint32_t a_h = st + a_off;
        const uint32_t a_l = a_h + TILE_PB;
        const uint32_t b_h = st + 2 * TILE_PB + b_off;
        const uint32_t b_l = b_h + TILE_PB;

        #pragma unroll
        for (int ks = 0; ks < 2; ks++) {
            uint32_t ah[4][4], al[4][4], bh[4][2], bl[4][2];
            #pragma unroll
            for (int mf = 0; mf < 4; mf++) {
                LDSM4(ah[mf], a_h + mf * 1280 + ks * 32);
                LDSM4(al[mf], a_l + mf * 1280 + ks * 32);
            }
            #pragma unroll
            for (int bg = 0; bg < 2; bg++) {
                uint32_t t[4];
                LDSM4(t, b_h + bg * 1280 + ks * 32);
                bh[2 * bg][0] = t[0]; bh[2 * bg][1] = t[1];
                bh[2 * bg + 1][0] = t[2]; bh[2 * bg + 1][1] = t[3];
                LDSM4(t, b_l + bg * 1280 + ks * 32);
                bl[2 * bg][0] = t[0]; bl[2 * bg][1] = t[1];
                bl[2 * bg + 1][0] = t[2]; bl[2 * bg + 1][1] = t[3];
            }
            #pragma unroll
            for (int mf = 0; mf < 4; mf++)
                #pragma unroll
                for (int nf = 0; nf < 4; nf++) {
                    MMA(acc[mf][nf], ah[mf], bh[nf]);
                    MMA(acc[mf][nf], ah[mf], bl[nf]);
                    MMA(acc[mf][nf], al[mf], bh[nf]);
                }
        }
        __syncthreads();
    }

    const int g = lane >> 2, t4 = lane & 3;
    #pragma unroll
    for (int mf = 0; mf < 4; mf++) {
        const int r = m0 + warp_m * 64 + mf * 16 + g;
        #pragma unroll
        for (int nf = 0; nf < 4; nf++) {
            const int c = n0 + warp_n * 32 + nf * 8 + t4 * 2;
            float2 v0 = make_float2(acc[mf][nf][0], acc[mf][nf][1]);
            float2 v1 = make_float2(acc[mf][nf][2], acc[mf][nf][3]);
            *reinterpret_cast<float2*>(C + (size_t)r * N + c) = v0;
            *reinterpret_cast<float2*>(C + (size_t)(r + 8) * N + c) = v1;
        }
    }
}

// ---------------------------------------------------------------------------
extern "C" void kernel_launch(void* const* d_in, const int* in_sizes, int n_in,
                              void* d_out, int out_size) {
    const float* x = (const float*)d_in[0];
    const float* w = (const float*)d_in[1];
    float* out = (float*)d_out;

    float *inv, *P;
    cudaGetSymbolAddress((void**)&inv, g_inv);
    cudaGetSymbolAddress((void**)&P, g_P);
    bf16 *nh, *nl, *yth, *ytl, *wth, *wtl, *gh, *gl, *hth, *htl;
    cudaGetSymbolAddress((void**)&nh, g_nh);   cudaGetSymbolAddress((void**)&nl, g_nl);
    cudaGetSymbolAddress((void**)&yth, g_yth); cudaGetSymbolAddress((void**)&ytl, g_ytl);
    cudaGetSymbolAddress((void**)&wth, g_wth); cudaGetSymbolAddress((void**)&wtl, g_wtl);
    cudaGetSymbolAddress((void**)&gh, g_gh);   cudaGetSymbolAddress((void**)&gl, g_gl);
    cudaGetSymbolAddress((void**)&hth, g_hth); cudaGetSymbolAddress((void**)&htl, g_htl);

    cudaFuncSetAttribute(gemm_hmma<0>, cudaFuncAttributeMaxDynamicSharedMemorySize, SMEM_DYN);
    cudaFuncSetAttribute(gemm_hmma<1>, cudaFuncAttributeMaxDynamicSharedMemorySize, SMEM_DYN);

    rownorm_inv<<<NROWS, 256>>>(x, inv);
    conv_x<<<dim3(DIM / 32, NROWS / 32), dim3(32, 8)>>>(x, inv, nh, nl, yth, ytl);
    conv_w<<<dim3(DIM / 32, DIM / 32), dim3(32, 8)>>>(w, wth, wtl);

    // G = y^T @ y (symmetric syrk): triangle blocks, split-K=8 -> 288 CTAs (2/SM)
    gemm_hmma<1><<<dim3(36, 1, 8), 256, SMEM_DYN>>>(
        yth, ytl, yth, ytl, P, (size_t)DIM * DIM, DIM, NROWS, NROWS / 8);
    combine_tri<<<dim3(16, 36), 256>>>(P, 8, gh, gl);

    // H^T = MM(W^T, G) : M=N=1024, K=1024, split-K=4 -> 256 CTAs (2/SM)
    gemm_hmma<0><<<dim3(8, 8, 4), 256, SMEM_DYN>>>(
        wth, wtl, gh, gl, P, (size_t)DIM * DIM, DIM, DIM, DIM / 4);
    combine_lin<<<DIM * DIM / 1024, 256>>>(P, 4, hth, htl);

    // out = MM(norm, H^T) : M=8192, N=1024, K=1024 (512 CTAs, 2/SM)
    gemm_hmma<0><<<dim3(8, 64, 1), 256, SMEM_DYN>>>(
        nh, nl, hth, htl, out, 0, DIM, DIM, DIM);
}

// round 6
// speedup vs baseline: 3.6246x; 1.1287x over previous
#include <cuda_runtime.h>
#include <cuda_bf16.h>
#include <cstdint>

// out = norm @ ((norm^T @ x) @ W),  norm = x / max(||x_row||, 1e-12)
// y = sqrt(inv)*x  =>  G = y^T @ y (symmetric, one operand).
// GEMMs: bf16 hi/lo split (3 products) on mma.sync.m16n8k16.
// 4-warp CTAs, warp tile 64x64 (2x fragment redundancy instead of 3x).

#define NROWS 8192
#define DIM   1024
typedef __nv_bfloat16 bf16;

// ---------------- scratch (device globals; no allocation allowed) ----------
__device__ float g_inv[NROWS];
__device__ bf16 g_nh[NROWS * DIM],  g_nl[NROWS * DIM];    // norm row-major
__device__ bf16 g_yth[DIM * NROWS], g_ytl[DIM * NROWS];   // y^T  [1024,8192]
__device__ bf16 g_wth[DIM * DIM],   g_wtl[DIM * DIM];     // W^T
__device__ bf16 g_gh[DIM * DIM],    g_gl[DIM * DIM];      // G
__device__ bf16 g_hth[DIM * DIM],   g_htl[DIM * DIM];     // H^T
__device__ float g_P[8 * DIM * DIM];                      // split-K partials

// 36 upper-triangle block pairs (bm >= bn) for an 8x8 block grid
__constant__ int2 c_tri[36] = {
    {0,0},{1,0},{1,1},{2,0},{2,1},{2,2},{3,0},{3,1},{3,2},{3,3},
    {4,0},{4,1},{4,2},{4,3},{4,4},{5,0},{5,1},{5,2},{5,3},{5,4},
    {5,5},{6,0},{6,1},{6,2},{6,3},{6,4},{6,5},{6,6},{7,0},{7,1},
    {7,2},{7,3},{7,4},{7,5},{7,6},{7,7}
};

// ---------------- PTX helpers ----------------------------------------------
__device__ __forceinline__ uint32_t smem_u32(const void* p) {
    uint32_t a;
    asm("{ .reg .u64 t; cvta.to.shared.u64 t, %1; cvt.u32.u64 %0, t; }" : "=r"(a) : "l"(p));
    return a;
}

#define CP16(saddr, gptr) \
    asm volatile("cp.async.cg.shared.global [%0], [%1], 16;" :: "r"(saddr), "l"(gptr))
#define CP_COMMIT() asm volatile("cp.async.commit_group;" ::: "memory")
#define CP_WAIT(n)  asm volatile("cp.async.wait_group %0;" :: "n"(n) : "memory")

#define LDSM4(r, addr) \
    asm volatile("ldmatrix.sync.aligned.m8n8.x4.shared.b16 {%0,%1,%2,%3}, [%4];" \
        : "=r"((r)[0]), "=r"((r)[1]), "=r"((r)[2]), "=r"((r)[3]) : "r"(addr))

#define MMA(c, a, b) \
    asm volatile("mma.sync.aligned.m16n8k16.row.col.f32.bf16.bf16.f32 " \
        "{%0,%1,%2,%3}, {%4,%5,%6,%7}, {%8,%9}, {%0,%1,%2,%3};" \
        : "+f"((c)[0]), "+f"((c)[1]), "+f"((c)[2]), "+f"((c)[3]) \
        : "r"((a)[0]), "r"((a)[1]), "r"((a)[2]), "r"((a)[3]), "r"((b)[0]), "r"((b)[1]))

// ---------------- small kernels --------------------------------------------
__global__ void rownorm_inv(const float* __restrict__ x, float* __restrict__ inv) {
    const int row = blockIdx.x;
    float4 v = reinterpret_cast<const float4*>(x + (size_t)row * DIM)[threadIdx.x];
    float s = v.x * v.x + v.y * v.y + v.z * v.z + v.w * v.w;
    #pragma unroll
    for (int o = 16; o > 0; o >>= 1) s += __shfl_down_sync(0xFFFFFFFFu, s, o);
    __shared__ float ws[8];
    if ((threadIdx.x & 31) == 0) ws[threadIdx.x >> 5] = s;
    __syncthreads();
    if (threadIdx.x == 0) {
        float t = 0.f;
        #pragma unroll
        for (int i = 0; i < 8; i++) t += ws[i];
        inv[row] = 1.0f / fmaxf(sqrtf(t), 1e-12f);
    }
}

__device__ __forceinline__ void split_bf(float v, bf16& h, bf16& l) {
    h = __float2bfloat16_rn(v);
    l = __float2bfloat16_rn(v - __bfloat162float(h));
}

__global__ void conv_x(const float* __restrict__ x, const float* __restrict__ inv,
                       bf16* __restrict__ nh, bf16* __restrict__ nl,
                       bf16* __restrict__ yth, bf16* __restrict__ ytl) {
    __shared__ float sy[32][33];
    const int c = blockIdx.x * 32 + threadIdx.x;
    const int r0 = blockIdx.y * 32;
    #pragma unroll
    for (int i = 0; i < 4; i++) {
        int rl = threadIdx.y + i * 8;
        int r = r0 + rl;
        float iv = inv[r];
        float v = x[(size_t)r * DIM + c];
        float nv = v * iv;
        bf16 h, l;
        split_bf(nv, h, l);
        nh[(size_t)r * DIM + c] = h;
        nl[(size_t)r * DIM + c] = l;
        sy[rl][threadIdx.x] = v * sqrtf(iv);
    }
    __syncthreads();
    const int tr = r0 + threadIdx.x;
    #pragma unroll
    for (int i = 0; i < 4; i++) {
        int cl = threadIdx.y + i * 8;
        int tc = blockIdx.x * 32 + cl;
        bf16 h, l;
        split_bf(sy[threadIdx.x][cl], h, l);
        yth[(size_t)tc * NROWS + tr] = h;
        ytl[(size_t)tc * NROWS + tr] = l;
    }
}

__global__ void conv_w(const float* __restrict__ w,
                       bf16* __restrict__ wth, bf16* __restrict__ wtl) {
    __shared__ float sw[32][33];
    const int c = blockIdx.x * 32 + threadIdx.x;
    const int r0 = blockIdx.y * 32;
    #pragma unroll
    for (int i = 0; i < 4; i++) {
        int rl = threadIdx.y + i * 8;
        sw[rl][threadIdx.x] = w[(size_t)(r0 + rl) * DIM + c];
    }
    __syncthreads();
    const int tr = r0 + threadIdx.x;
    #pragma unroll
    for (int i = 0; i < 4; i++) {
        int cl = threadIdx.y + i * 8;
        int tc = blockIdx.x * 32 + cl;
        bf16 h, l;
        split_bf(sw[threadIdx.x][cl], h, l);
        wth[(size_t)tc * DIM + tr] = h;
        wtl[(size_t)tc * DIM + tr] = l;
    }
}

__global__ void combine_tri(const float* __restrict__ P, int np,
                            bf16* __restrict__ hi, bf16* __restrict__ lo) {
    const int2 bp = c_tri[blockIdx.y];
    const int idx = (blockIdx.x * 256 + threadIdx.x) * 4;
    const int R = bp.x * 128 + (idx >> 7);
    const int C = bp.y * 128 + (idx & 127);
    const size_t o = (size_t)R * DIM + C;
    float v[4] = {0.f, 0.f, 0.f, 0.f};
    for (int p = 0; p < np; p++) {
        float4 a = *reinterpret_cast<const float4*>(P + (size_t)p * DIM * DIM + o);
        v[0] += a.x; v[1] += a.y; v[2] += a.z; v[3] += a.w;
    }
    bf16 h[4], l[4];
    #pragma unroll
    for (int j = 0; j < 4; j++) split_bf(v[j], h[j], l[j]);
    *reinterpret_cast<uint2*>(hi + o) = *reinterpret_cast<const uint2*>(h);
    *reinterpret_cast<uint2*>(lo + o) = *reinterpret_cast<const uint2*>(l);
    if (bp.x != bp.y) {
        #pragma unroll
        for (int j = 0; j < 4; j++) {
            hi[(size_t)(C + j) * DIM + R] = h[j];
            lo[(size_t)(C + j) * DIM + R] = l[j];
        }
    }
}

__global__ void combine_lin(const float* __restrict__ P, int np,
                            bf16* __restrict__ hi, bf16* __restrict__ lo) {
    const int i = (blockIdx.x * 256 + threadIdx.x) * 4;
    float v[4] = {0.f, 0.f, 0.f, 0.f};
    for (int p = 0; p < np; p++) {
        float4 a = *reinterpret_cast<const float4*>(P + (size_t)p * DIM * DIM + i);
        v[0] += a.x; v[1] += a.y; v[2] += a.z; v[3] += a.w;
    }
    bf16 h[4], l[4];
    #pragma unroll
    for (int j = 0; j < 4; j++) split_bf(v[j], h[j], l[j]);
    *reinterpret_cast<uint2*>(hi + i) = *reinterpret_cast<const uint2*>(h);
    *reinterpret_cast<uint2*>(lo + i) = *reinterpret_cast<const uint2*>(l);
}

// ---------------- HMMA GEMM: C[m,n] = sum_k A[m,k]*B[n,k], hi/lo 3-product --
// CTA tile 128x128, BK=32, 4 warps (2m x 2n), warp tile 64x64.
#define TILE_PB  10240                // 128 * 80
#define STAGE_B  (4 * TILE_PB)        // 40960
#define SMEM_DYN (2 * STAGE_B)        // 81920

__device__ __forceinline__ void stage_load(uint32_t s_stage,
                                           const bf16* __restrict__ Ah, const bf16* __restrict__ Al,
                                           const bf16* __restrict__ Bh, const bf16* __restrict__ Bl,
                                           int m0, int n0, int k, int ldk, int tid) {
    #pragma unroll
    for (int i = 0; i < 4; i++) {
        const int idx = tid + i * 128;        // 0..511
        const int row = idx >> 2;             // 0..127
        const int cb = (idx & 3) * 16;        // 0,16,32,48 bytes
        const uint32_t so = s_stage + row * 80 + cb;
        const size_t goA = ((size_t)(m0 + row) * ldk + k) * 2 + cb;
        const size_t goB = ((size_t)(n0 + row) * ldk + k) * 2 + cb;
        CP16(so,               (const char*)Ah + goA);
        CP16(so + TILE_PB,     (const char*)Al + goA);
        CP16(so + 2 * TILE_PB, (const char*)Bh + goB);
        CP16(so + 3 * TILE_PB, (const char*)Bl + goB);
    }
}

template <int TRI>
__global__ __launch_bounds__(128, 2)
void gemm_hmma(const bf16* __restrict__ Ah, const bf16* __restrict__ Al,
               const bf16* __restrict__ Bh, const bf16* __restrict__ Bl,
               float* __restrict__ Cbase, size_t cplane,
               int N, int ldk, int ksplit) {
    extern __shared__ char smem[];
    const uint32_t su = smem_u32(smem);
    const int tid = threadIdx.x;
    const int lane = tid & 31;
    const int wid = tid >> 5;
    const int warp_m = wid & 1;     // 2 warps in M (64 rows each)
    const int warp_n = wid >> 1;    // 2 warps in N (64 cols each)
    int m0, n0;
    if (TRI) {
        const int2 bp = c_tri[blockIdx.x];
        m0 = bp.x * 128; n0 = bp.y * 128;
    } else {
        m0 = blockIdx.y * 128; n0 = blockIdx.x * 128;
    }
    const int k0 = blockIdx.z * ksplit;
    float* C = Cbase + (size_t)blockIdx.z * cplane;

    float acc[4][8][4];
    #pragma unroll
    for (int i = 0; i < 4; i++)
        #pragma unroll
        for (int j = 0; j < 8; j++)
            #pragma unroll
            for (int q = 0; q < 4; q++) acc[i][j][q] = 0.f;

    const uint32_t a_off = (uint32_t)(warp_m * 64 + (lane & 15)) * 80 + ((lane >> 4) << 4);
    const uint32_t b_off = (uint32_t)(warp_n * 64 + ((lane >> 4) << 3) + (lane & 7)) * 80
                         + (((lane >> 3) & 1) << 4);

    const int NIT = ksplit / 32;
    stage_load(su, Ah, Al, Bh, Bl, m0, n0, k0, ldk, tid);
    CP_COMMIT();

    for (int it = 0; it < NIT; it++) {
        if (it + 1 < NIT) {
            stage_load(su + ((it + 1) & 1) * STAGE_B, Ah, Al, Bh, Bl,
                       m0, n0, k0 + (it + 1) * 32, ldk, tid);
            CP_COMMIT();
            CP_WAIT(1);
        } else {
            CP_WAIT(0);
        }
        __syncthreads();

        const uint32_t st = su + (it & 1) * STAGE_B;
        const uint32_t a_h = st + a_off;
        const uint32_t a_l = a_h + TILE_PB;
        const uint32_t b_h = st + 2 * TILE_PB + b_off;
        const uint32_t b_l = b_h + TILE_PB;

        #pragma unroll
        for (int ks = 0; ks < 2; ks++) {
            uint32_t ah[4][4], al[4][4], bh[8][2], bl[8][2];
            #pragma unroll
            for (int mf = 0; mf < 4; mf++) {
                LDSM4(ah[mf], a_h + mf * 1280 + ks * 32);
                LDSM4(al[mf], a_l + mf * 1280 + ks * 32);
            }
            #pragma unroll
            for (int bg = 0; bg < 4; bg++) {
                uint32_t t[4];
                LDSM4(t, b_h + bg * 1280 + ks * 32);
                bh[2 * bg][0] = t[0]; bh[2 * bg][1] = t[1];
                bh[2 * bg + 1][0] = t[2]; bh[2 * bg + 1][1] = t[3];
                LDSM4(t, b_l + bg * 1280 + ks * 32);
                bl[2 * bg][0] = t[0]; bl[2 * bg][1] = t[1];
                bl[2 * bg + 1][0] = t[2]; bl[2 * bg + 1][1] = t[3];
            }
            #pragma unroll
            for (int mf = 0; mf < 4; mf++)
                #pragma unroll
                for (int nf = 0; nf < 8; nf++) {
                    MMA(acc[mf][nf], ah[mf], bh[nf]);
                    MMA(acc[mf][nf], ah[mf], bl[nf]);
                    MMA(acc[mf][nf], al[mf], bh[nf]);
                }
        }
        __syncthreads();
    }

    const int g = lane >> 2, t4 = lane & 3;
    #pragma unroll
    for (int mf = 0; mf < 4; mf++) {
        const int r = m0 + warp_m * 64 + mf * 16 + g;
        #pragma unroll
        for (int nf = 0; nf < 8; nf++) {
            const int c = n0 + warp_n * 64 + nf * 8 + t4 * 2;
            float2 v0 = make_float2(acc[mf][nf][0], acc[mf][nf][1]);
            float2 v1 = make_float2(acc[mf][nf][2], acc[mf][nf][3]);
            *reinterpret_cast<float2*>(C + (size_t)r * N + c) = v0;
            *reinterpret_cast<float2*>(C + (size_t)(r + 8) * N + c) = v1;
        }
    }
}

// ---------------------------------------------------------------------------
extern "C" void kernel_launch(void* const* d_in, const int* in_sizes, int n_in,
                              void* d_out, int out_size) {
    const float* x = (const float*)d_in[0];
    const float* w = (const float*)d_in[1];
    float* out = (float*)d_out;

    float *inv, *P;
    cudaGetSymbolAddress((void**)&inv, g_inv);
    cudaGetSymbolAddress((void**)&P, g_P);
    bf16 *nh, *nl, *yth, *ytl, *wth, *wtl, *gh, *gl, *hth, *htl;
    cudaGetSymbolAddress((void**)&nh, g_nh);   cudaGetSymbolAddress((void**)&nl, g_nl);
    cudaGetSymbolAddress((void**)&yth, g_yth); cudaGetSymbolAddress((void**)&ytl, g_ytl);
    cudaGetSymbolAddress((void**)&wth, g_wth); cudaGetSymbolAddress((void**)&wtl, g_wtl);
    cudaGetSymbolAddress((void**)&gh, g_gh);   cudaGetSymbolAddress((void**)&gl, g_gl);
    cudaGetSymbolAddress((void**)&hth, g_hth); cudaGetSymbolAddress((void**)&htl, g_htl);

    cudaFuncSetAttribute(gemm_hmma<0>, cudaFuncAttributeMaxDynamicSharedMemorySize, SMEM_DYN);
    cudaFuncSetAttribute(gemm_hmma<1>, cudaFuncAttributeMaxDynamicSharedMemorySize, SMEM_DYN);

    rownorm_inv<<<NROWS, 256>>>(x, inv);
    conv_x<<<dim3(DIM / 32, NROWS / 32), dim3(32, 8)>>>(x, inv, nh, nl, yth, ytl);
    conv_w<<<dim3(DIM / 32, DIM / 32), dim3(32, 8)>>>(w, wth, wtl);

    // G = y^T @ y (symmetric syrk): triangle blocks, split-K=8 -> 288 CTAs
    gemm_hmma<1><<<dim3(36, 1, 8), 128, SMEM_DYN>>>(
        yth, ytl, yth, ytl, P, (size_t)DIM * DIM, DIM, NROWS, NROWS / 8);
    combine_tri<<<dim3(16, 36), 256>>>(P, 8, gh, gl);

    // H^T = MM(W^T, G) : M=N=1024, K=1024, split-K=4 -> 256 CTAs
    gemm_hmma<0><<<dim3(8, 8, 4), 128, SMEM_DYN>>>(
        wth, wtl, gh, gl, P, (size_t)DIM * DIM, DIM, DIM, DIM / 4);
    combine_lin<<<DIM * DIM / 1024, 256>>>(P, 4, hth, htl);

    // out = MM(norm, H^T) : M=8192, N=1024, K=1024 (512 CTAs)
    gemm_hmma<0><<<dim3(8, 64, 1), 128, SMEM_DYN>>>(
        nh, nl, hth, htl, out, 0, DIM, DIM, DIM);
}